// round 7
// baseline (speedup 1.0000x reference)
#include <cuda_runtime.h>
#include <cstdint>

#define BB 64
#define FF 128
#define LL 8192
#define KK 16
#define TILE 128
#define NTILES (LL / TILE)      // 64
#define RS 132                  // padded SMEM row stride (floats)
#define TSZ (64 * RS)           // 8448 floats per tile buffer

typedef unsigned long long u64;

__device__ __forceinline__ u64 fma2(u64 a, u64 b, u64 c) {
    u64 d;
    asm("fma.rn.f32x2 %0, %1, %2, %3;" : "=l"(d) : "l"(a), "l"(b), "l"(c));
    return d;
}
__device__ __forceinline__ u64 pack2(float lo, float hi) {
    u64 d; asm("mov.b64 %0, {%1, %2};" : "=l"(d) : "f"(lo), "f"(hi)); return d;
}
__device__ __forceinline__ void unpack2(u64 v, float& lo, float& hi) {
    asm("mov.b64 {%0, %1}, %2;" : "=f"(lo), "=f"(hi) : "l"(v));
}
__device__ __forceinline__ void stcs4(float* p, float4 v) {
    asm volatile("st.global.cs.v4.f32 [%0], {%1,%2,%3,%4};"
                 :: "l"(p), "f"(v.x), "f"(v.y), "f"(v.z), "f"(v.w) : "memory");
}
__device__ __forceinline__ float4 max4(float4 a, float4 b) {
    return make_float4(fmaxf(a.x, b.x), fmaxf(a.y, b.y),
                       fmaxf(a.z, b.z), fmaxf(a.w, b.w));
}

// ---- cluster / mbarrier helpers ----
__device__ __forceinline__ uint32_t smem_u32(const void* p) {
    uint32_t a;
    asm("{ .reg .u64 t; cvta.to.shared.u64 t, %1; cvt.u32.u64 %0, t; }"
        : "=r"(a) : "l"(p));
    return a;
}
__device__ __forceinline__ uint32_t mapa_rank(uint32_t addr, uint32_t rank) {
    uint32_t r;
    asm("mapa.shared::cluster.u32 %0, %1, %2;" : "=r"(r) : "r"(addr), "r"(rank));
    return r;
}
__device__ __forceinline__ void mbar_init(uint32_t a, uint32_t cnt) {
    asm volatile("mbarrier.init.shared.b64 [%0], %1;" :: "r"(a), "r"(cnt) : "memory");
}
__device__ __forceinline__ void mbar_arrive_rel_cluster(uint32_t a) {
    asm volatile("mbarrier.arrive.release.cluster.shared::cluster.b64 _, [%0];"
                 :: "r"(a) : "memory");
}
__device__ __forceinline__ void mbar_wait_acq_cluster(uint32_t a, uint32_t par) {
    asm volatile(
        "{\n\t"
        ".reg .pred P1;\n\t"
        "LAB_W_%=:\n\t"
        "mbarrier.try_wait.parity.acquire.cluster.shared::cta.b64 P1, [%0], %1;\n\t"
        "@P1 bra.uni LAB_D_%=;\n\t"
        "bra.uni LAB_W_%=;\n\t"
        "LAB_D_%=:\n\t"
        "}"
        :: "r"(a), "r"(par) : "memory");
}
__device__ __forceinline__ void st_cluster_f32(uint32_t addr, float v) {
    asm volatile("st.shared::cluster.f32 [%0], %1;" :: "r"(addr), "f"(v) : "memory");
}

// ---------------------------------------------------------------------------
// conv: one column half (16 quads, 64 cols) for fixed filter f. f32x2 FMAs.
// ---------------------------------------------------------------------------
__device__ __forceinline__ void conv_do(
    int qh, const float* __restrict__ xs, const float* __restrict__ xsh,
    const u64* __restrict__ w2, u64 bias2, float* __restrict__ irow)
{
#pragma unroll
    for (int j = 0; j < 16; ++j) {
        const int lt4 = qh * 64 + 4 * j;     // even
        u64 P[18];
#pragma unroll
        for (int m = 0; m < 18; ++m) {
            int base = lt4 + m;              // parity == m parity
            P[m] = (m & 1) ? *(const u64*)(xsh + (base - 1))
                           : *(const u64*)(xs + base);
        }
        u64 a01 = bias2, a23 = bias2;
#pragma unroll
        for (int k = 0; k < KK; ++k) {
            a01 = fma2(w2[k], P[k],     a01);
            a23 = fma2(w2[k], P[k + 2], a23);
        }
        float o0, o1, o2, o3;
        unpack2(a01, o0, o1);
        unpack2(a23, o2, o3);
        *(float4*)(irow + lt4) = make_float4(o0, o1, o2, o3);
    }
}

// ---------------------------------------------------------------------------
// Fused conv + LIF + coalesced streaming stores + clustered logits combine.
// Grid 128 = (batch, filter-half); cluster (2,1,1) pairs the two halves.
//   tid   0- 63 : chain warps  — LIF recurrence -> v_pre tiles in SMEM
//   tid  64-191 : conv warps   — f32x2 conv of tile T+1 (double-buffered)
//   tid 192-255 : flush warps  — STG I(T), v_pre/v/s(T-1) (derive v,s);
//                 half-max -> DSMEM handshake -> rank0 writes final logits
// ---------------------------------------------------------------------------
__global__ __launch_bounds__(256, 1) __cluster_dims__(2, 1, 1)
void snn_fused(
    const float* __restrict__ x, const float* __restrict__ W,
    const float* __restrict__ bias,
    float* __restrict__ I_out, float* __restrict__ vpre_out,
    float* __restrict__ v_out, float* __restrict__ s_out,
    float* __restrict__ logits)
{
    extern __shared__ float sm[];
    float* Ibuf = sm;                 // 2*TSZ
    float* tvp  = sm + 2 * TSZ;       // 2*TSZ
    float* xs   = sm + 4 * TSZ;       // 144 (143 used)
    float* xsh  = xs + 144;           // 144
    float* red  = xsh + 144;          // 256
    float* peer = red + 256;          // 256: 2 slots x 128 (used on rank 0)
    u64*  mbars = (u64*)(peer + 256); // [full0, full1, empty0, empty1]

    const int tid   = threadIdx.x;
    const int b     = blockIdx.x >> 1;
    const int h     = blockIdx.x & 1;           // == cluster rank
    const int frow0 = b * FF + h * 64;
    const float* __restrict__ xb = x + (size_t)b * LL;

    const uint32_t mbar_base = smem_u32(mbars);
    if (tid == 0) {
        mbar_init(mbar_base + 0, 1);   // full0
        mbar_init(mbar_base + 8, 1);   // full1
        mbar_init(mbar_base + 16, 1);  // empty0
        mbar_init(mbar_base + 24, 1);  // empty1
    }

    // conv-thread persistent state (filter index is batch-INDEPENDENT)
    u64 w2[KK];
    u64 bias2 = 0;
    int f_loc = 0, qh = 0;
    if (tid >= 64 && tid < 192) {
        const int p = tid - 64;
        f_loc = p >> 1; qh = p & 1;
        const int fflt = h * 64 + f_loc;        // filter index 0..127
#pragma unroll
        for (int k = 0; k < KK; ++k) {
            const float w = W[fflt * KK + k];
            w2[k] = pack2(w, w);
        }
        const float bv = bias[fflt];
        bias2 = pack2(bv, bv);
    }

    // flush-thread persistent remote addresses
    uint32_t peer_rmt = 0, full_rmt0 = 0, full_rmt1 = 0;
    uint32_t empty_rmt0 = 0, empty_rmt1 = 0;
    if (tid >= 192) {
        const uint32_t peer_base = smem_u32(peer);
        peer_rmt   = mapa_rank(peer_base, 0);
        full_rmt0  = mapa_rank(mbar_base + 0, 0);
        full_rmt1  = mapa_rank(mbar_base + 8, 0);
        empty_rmt0 = mapa_rank(mbar_base + 16, 1);
        empty_rmt1 = mapa_rank(mbar_base + 24, 1);
    }

    // ---- prologue: stage xs(tile0), conv tile0 -> Ibuf[0] ----
    if (tid >= 64 && tid < 192) {
        const int p = tid - 64;
        {
            int g = p - 15;
            float val = (g >= 0) ? xb[g] : 0.0f;
            xs[p] = val;
            if (p >= 1) xsh[p - 1] = val;
        }
        if (p < 15) {
            int idx = 128 + p;
            float val = xb[idx - 15];
            xs[idx] = val;
            xsh[idx - 1] = val;
        }
        asm volatile("bar.sync 1, 128;" ::: "memory");
        conv_do(qh, xs, xsh, w2, bias2, Ibuf + f_loc * RS);
    }
    __syncthreads();
    // mbarrier inits of BOTH CTAs visible before any remote arrive
    asm volatile("barrier.cluster.arrive.aligned;" ::: "memory");
    asm volatile("barrier.cluster.wait.aligned;" ::: "memory");

    float vchain = 0.0f;

    for (int T = 0; T < NTILES; ++T) {
        const int buf = T & 1;
        if (tid < 64) {
            // ---------------- chain ----------------
            const float* ir = Ibuf + buf * TSZ + tid * RS;
            float* vr = tvp + buf * TSZ + tid * RS;
            float4 cur = *(const float4*)ir;
#pragma unroll
            for (int q = 0; q < 32; ++q) {
                float4 nxt = (q < 31) ? *(const float4*)(ir + 4 * (q + 1)) : cur;
                const float c0 = 0.2f * cur.x, c1 = 0.2f * cur.y;
                const float c2 = 0.2f * cur.z, c3 = 0.2f * cur.w;
                float vp0 = fmaf(vchain, 0.8f, c0);
                vchain = (vp0 >= 1.0f) ? 0.0f : vp0;
                float vp1 = fmaf(vchain, 0.8f, c1);
                vchain = (vp1 >= 1.0f) ? 0.0f : vp1;
                float vp2 = fmaf(vchain, 0.8f, c2);
                vchain = (vp2 >= 1.0f) ? 0.0f : vp2;
                float vp3 = fmaf(vchain, 0.8f, c3);
                vchain = (vp3 >= 1.0f) ? 0.0f : vp3;
                *(float4*)(vr + 4 * q) = make_float4(vp0, vp1, vp2, vp3);
                cur = nxt;
            }
        } else if (tid < 192) {
            // ---------------- conv ----------------
            const int p = tid - 64;
            if (T + 1 < NTILES) {
                {
                    int g = (T + 1) * TILE - 15 + p;   // >= 113, valid
                    float val = xb[g];
                    xs[p] = val;
                    if (p >= 1) xsh[p - 1] = val;
                }
                if (p < 15) {
                    int idx = 128 + p;
                    float val = xb[(T + 1) * TILE - 15 + idx];
                    xs[idx] = val;
                    xsh[idx - 1] = val;
                }
                asm volatile("bar.sync 1, 128;" ::: "memory");
                conv_do(qh, xs, xsh, w2, bias2,
                        Ibuf + ((T + 1) & 1) * TSZ + f_loc * RS);
            }
        } else {
            // ---------------- flush ----------------
            const int ft = tid - 192;
            const int r0 = ft >> 5, tq = ft & 31;    // warp covers full rows
            const float* ib  = Ibuf + buf * TSZ;
            const float* vpb = tvp + (buf ^ 1) * TSZ;
            const size_t tcol = (size_t)T * TILE + tq * 4;
            const size_t pcol = (size_t)(T - 1) * TILE + tq * 4;
            float4 mx = make_float4(-1e30f, -1e30f, -1e30f, -1e30f);
#pragma unroll
            for (int i = 0; i < 32; ++i) {
                const int r = r0 + 2 * i;
                const size_t grow = (size_t)(frow0 + r) * LL;
                float4 iq = *(const float4*)(ib + r * RS + tq * 4);
                stcs4(I_out + grow + tcol, iq);
                if (T >= 1) {
                    float4 vq = *(const float4*)(vpb + r * RS + tq * 4);
                    float4 sq, vn;
                    sq.x = (vq.x >= 1.0f) ? 1.0f : 0.0f;
                    sq.y = (vq.y >= 1.0f) ? 1.0f : 0.0f;
                    sq.z = (vq.z >= 1.0f) ? 1.0f : 0.0f;
                    sq.w = (vq.w >= 1.0f) ? 1.0f : 0.0f;
                    vn.x = (vq.x >= 1.0f) ? 0.0f : vq.x;
                    vn.y = (vq.y >= 1.0f) ? 0.0f : vq.y;
                    vn.z = (vq.z >= 1.0f) ? 0.0f : vq.z;
                    vn.w = (vq.w >= 1.0f) ? 0.0f : vq.w;
                    stcs4(vpre_out + grow + pcol, vq);
                    stcs4(v_out    + grow + pcol, vn);
                    stcs4(s_out    + grow + pcol, sq);
                    mx = max4(mx, vq);
                }
            }
            if (T >= 1) {
                const int S = T - 1;                 // logical logits tile
                const int s = S & 1;
                *(float4*)(red + ft * 4) = mx;
                asm volatile("bar.sync 3, 64;" ::: "memory");
                if (ft < 32) {                        // warp 6 only
                    float4 a = max4(*(float4*)(red + ft * 4),
                                    *(float4*)(red + (32 + ft) * 4));
                    if (h == 1) {
                        if (ft == 0 && S >= 2)
                            mbar_wait_acq_cluster(mbar_base + 16 + 8 * s,
                                                  ((S - 2) >> 1) & 1);
                        __syncwarp();
                        uint32_t dst = peer_rmt + (uint32_t)(s * 128 + ft * 4) * 4;
                        st_cluster_f32(dst,      a.x);
                        st_cluster_f32(dst + 4,  a.y);
                        st_cluster_f32(dst + 8,  a.z);
                        st_cluster_f32(dst + 12, a.w);
                        __syncwarp();
                        if (ft == 0)
                            mbar_arrive_rel_cluster(s ? full_rmt1 : full_rmt0);
                    } else {
                        if (ft == 0)
                            mbar_wait_acq_cluster(mbar_base + 8 * s, (S >> 1) & 1);
                        __syncwarp();
                        float4 p = *(float4*)(peer + s * 128 + ft * 4);
                        float4 m = max4(a, p);
                        m.x -= 1.0f; m.y -= 1.0f; m.z -= 1.0f; m.w -= 1.0f;
                        stcs4(logits + (size_t)b * LL + (size_t)S * TILE + ft * 4, m);
                        __syncwarp();
                        if (ft == 0)
                            mbar_arrive_rel_cluster(s ? empty_rmt1 : empty_rmt0);
                    }
                }
            }
        }
        __syncthreads();
    }

    // ---- epilogue: flush v_pre/v/s + logits of tile 63 (buffer 1) ----
    if (tid >= 192) {
        const int ft = tid - 192;
        const int r0 = ft >> 5, tq = ft & 31;
        const float* vpb = tvp + ((NTILES - 1) & 1) * TSZ;
        const size_t pcol = (size_t)(NTILES - 1) * TILE + tq * 4;
        float4 mx = make_float4(-1e30f, -1e30f, -1e30f, -1e30f);
#pragma unroll
        for (int i = 0; i < 32; ++i) {
            const int r = r0 + 2 * i;
            const size_t grow = (size_t)(frow0 + r) * LL;
            float4 vq = *(const float4*)(vpb + r * RS + tq * 4);
            float4 sq, vn;
            sq.x = (vq.x >= 1.0f) ? 1.0f : 0.0f;
            sq.y = (vq.y >= 1.0f) ? 1.0f : 0.0f;
            sq.z = (vq.z >= 1.0f) ? 1.0f : 0.0f;
            sq.w = (vq.w >= 1.0f) ? 1.0f : 0.0f;
            vn.x = (vq.x >= 1.0f) ? 0.0f : vq.x;
            vn.y = (vq.y >= 1.0f) ? 0.0f : vq.y;
            vn.z = (vq.z >= 1.0f) ? 0.0f : vq.z;
            vn.w = (vq.w >= 1.0f) ? 0.0f : vq.w;
            stcs4(vpre_out + grow + pcol, vq);
            stcs4(v_out    + grow + pcol, vn);
            stcs4(s_out    + grow + pcol, sq);
            mx = max4(mx, vq);
        }
        const int S = NTILES - 1;                    // 63
        const int s = S & 1;                         // 1
        *(float4*)(red + ft * 4) = mx;
        asm volatile("bar.sync 3, 64;" ::: "memory");
        if (ft < 32) {
            float4 a = max4(*(float4*)(red + ft * 4),
                            *(float4*)(red + (32 + ft) * 4));
            if (h == 1) {
                if (ft == 0)
                    mbar_wait_acq_cluster(mbar_base + 16 + 8 * s,
                                          ((S - 2) >> 1) & 1);
                __syncwarp();
                uint32_t dst = peer_rmt + (uint32_t)(s * 128 + ft * 4) * 4;
                st_cluster_f32(dst,      a.x);
                st_cluster_f32(dst + 4,  a.y);
                st_cluster_f32(dst + 8,  a.z);
                st_cluster_f32(dst + 12, a.w);
                __syncwarp();
                if (ft == 0)
                    mbar_arrive_rel_cluster(s ? full_rmt1 : full_rmt0);
            } else {
                if (ft == 0)
                    mbar_wait_acq_cluster(mbar_base + 8 * s, (S >> 1) & 1);
                __syncwarp();
                float4 p = *(float4*)(peer + s * 128 + ft * 4);
                float4 m = max4(a, p);
                m.x -= 1.0f; m.y -= 1.0f; m.z -= 1.0f; m.w -= 1.0f;
                stcs4(logits + (size_t)b * LL + (size_t)S * TILE + ft * 4, m);
                __syncwarp();
                // no empty arrive needed: last use of the slot
            }
        }
    }
    __syncthreads();
    // no CTA may exit while its peer may still target this CTA's SMEM
    asm volatile("barrier.cluster.arrive.aligned;" ::: "memory");
    asm volatile("barrier.cluster.wait.aligned;" ::: "memory");
}

extern "C" void kernel_launch(void* const* d_in, const int* in_sizes, int n_in,
                              void* d_out, int out_size)
{
    const float* x    = (const float*)d_in[0];
    const float* W    = (const float*)d_in[1];
    const float* bias = (const float*)d_in[2];
    float* out = (float*)d_out;

    const size_t N = (size_t)BB * FF * LL;   // 67,108,864
    float* I    = out;
    float* vpre = out + N;
    float* vv   = out + 2 * N;
    float* ss   = out + 3 * N;
    float* lg   = out + 4 * N;

    const int smem_bytes =
        (4 * TSZ + 144 + 144 + 256 + 256) * sizeof(float) + 32;  // ~135.3KB
    cudaFuncSetAttribute(snn_fused,
                         cudaFuncAttributeMaxDynamicSharedMemorySize, smem_bytes);

    snn_fused<<<128, 256, smem_bytes>>>(x, W, bias, I, vpre, vv, ss, lg);
}

// round 8
// speedup vs baseline: 1.2421x; 1.2421x over previous
#include <cuda_runtime.h>

#define BB 64
#define FF 128
#define LL 8192
#define KK 16
#define TILE 64
#define NTILES (LL / TILE)      // 128
#define RS 68                   // padded SMEM row stride (floats)
#define TSZ (32 * RS)           // 2176 floats per tile buffer (32 filters)

typedef unsigned long long u64;

__device__ float g_partial[256 * LL];   // per-(batch,quarter) partial max (8MB)

__device__ __forceinline__ u64 fma2(u64 a, u64 b, u64 c) {
    u64 d;
    asm("fma.rn.f32x2 %0, %1, %2, %3;" : "=l"(d) : "l"(a), "l"(b), "l"(c));
    return d;
}
__device__ __forceinline__ u64 pack2(float lo, float hi) {
    u64 d; asm("mov.b64 %0, {%1, %2};" : "=l"(d) : "f"(lo), "f"(hi)); return d;
}
__device__ __forceinline__ void unpack2(u64 v, float& lo, float& hi) {
    asm("mov.b64 {%0, %1}, %2;" : "=f"(lo), "=f"(hi) : "l"(v));
}
__device__ __forceinline__ void stcs4(float* p, float4 v) {
    asm volatile("st.global.cs.v4.f32 [%0], {%1,%2,%3,%4};"
                 :: "l"(p), "f"(v.x), "f"(v.y), "f"(v.z), "f"(v.w) : "memory");
}
__device__ __forceinline__ float4 max4(float4 a, float4 b) {
    return make_float4(fmaxf(a.x, b.x), fmaxf(a.y, b.y),
                       fmaxf(a.z, b.z), fmaxf(a.w, b.w));
}

// ---------------------------------------------------------------------------
// conv: one column half (8 quads, 32 cols) for fixed filter. f32x2 FMAs.
// xs[p] = x[tile*64 - 15 + p]; xsh[q] = xs[q+1] (odd-parity pairs).
// ---------------------------------------------------------------------------
__device__ __forceinline__ void conv_do(
    int qh, const float* __restrict__ xs, const float* __restrict__ xsh,
    const u64* __restrict__ w2, u64 bias2, float* __restrict__ irow)
{
#pragma unroll
    for (int j = 0; j < 8; ++j) {
        const int lt4 = qh * 32 + 4 * j;     // even
        u64 P[18];
#pragma unroll
        for (int m = 0; m < 18; ++m) {
            int base = lt4 + m;              // parity == m parity
            P[m] = (m & 1) ? *(const u64*)(xsh + (base - 1))
                           : *(const u64*)(xs + base);
        }
        u64 a01 = bias2, a23 = bias2;
#pragma unroll
        for (int k = 0; k < KK; ++k) {
            a01 = fma2(w2[k], P[k],     a01);
            a23 = fma2(w2[k], P[k + 2], a23);
        }
        float o0, o1, o2, o3;
        unpack2(a01, o0, o1);
        unpack2(a23, o2, o3);
        *(float4*)(irow + lt4) = make_float4(o0, o1, o2, o3);
    }
}

// ---------------------------------------------------------------------------
// Fused conv + LIF + coalesced streaming stores + fused logits partial max.
// Grid 256 = (batch, filter-quarter); 128 threads; 2 blocks per SM so the
// two barrier domains desynchronize and keep the store stream smooth.
//   tid   0- 31 : chain warp  — LIF recurrence -> v_pre tiles in SMEM
//   tid  32- 95 : conv warps  — f32x2 conv of tile T+1 (double-buffered)
//   tid  96-127 : flush warp  — STG I(T); STG v_pre/v/s(T-1) with derive;
//                               column-max -> g_partial
// ---------------------------------------------------------------------------
__global__ __launch_bounds__(128, 2) void snn_fused(
    const float* __restrict__ x, const float* __restrict__ W,
    const float* __restrict__ bias,
    float* __restrict__ I_out, float* __restrict__ vpre_out,
    float* __restrict__ v_out, float* __restrict__ s_out)
{
    extern __shared__ float sm[];
    float* Ibuf = sm;                 // 2*TSZ
    float* tvp  = sm + 2 * TSZ;       // 2*TSZ
    float* xs   = sm + 4 * TSZ;       // 84 (79 used)
    float* xsh  = xs + 84;            // 84
    float* red  = xsh + 84;           // 128

    const int tid   = threadIdx.x;
    const int b     = blockIdx.x >> 2;
    const int qtr   = blockIdx.x & 3;
    const int frow0 = b * FF + qtr * 32;        // OUTPUT row base
    const float* __restrict__ xb = x + (size_t)b * LL;
    float* __restrict__ prow = g_partial + (size_t)blockIdx.x * LL;

    // conv-thread persistent state (filter index is batch-INDEPENDENT)
    u64 w2[KK];
    u64 bias2 = 0;
    int f_loc = 0, qh = 0;
    if (tid >= 32 && tid < 96) {
        const int p = tid - 32;
        f_loc = p >> 1; qh = p & 1;
        const int fflt = qtr * 32 + f_loc;      // filter index 0..127
#pragma unroll
        for (int k = 0; k < KK; ++k) {
            const float w = W[fflt * KK + k];
            w2[k] = pack2(w, w);
        }
        const float bv = bias[fflt];
        bias2 = pack2(bv, bv);
    }

    // ---- prologue: stage xs(tile0), conv tile0 -> Ibuf[0] ----
    if (tid >= 32 && tid < 96) {
        const int p = tid - 32;                 // 0..63
        {
            int g = p - 15;
            float val = (g >= 0) ? xb[g] : 0.0f;
            xs[p] = val;
            if (p >= 1) xsh[p - 1] = val;
        }
        if (p < 15) {
            int idx = 64 + p;                   // 64..78
            float val = xb[idx - 15];
            xs[idx] = val;
            xsh[idx - 1] = val;
        }
        asm volatile("bar.sync 1, 64;" ::: "memory");
        conv_do(qh, xs, xsh, w2, bias2, Ibuf + f_loc * RS);
    }
    __syncthreads();

    float vchain = 0.0f;

    for (int T = 0; T < NTILES; ++T) {
        const int buf = T & 1;
        if (tid < 32) {
            // ---------------- chain ----------------
            const float* ir = Ibuf + buf * TSZ + tid * RS;
            float* vr = tvp + buf * TSZ + tid * RS;
            float4 cur = *(const float4*)ir;
#pragma unroll
            for (int q = 0; q < 16; ++q) {
                float4 nxt = (q < 15) ? *(const float4*)(ir + 4 * (q + 1)) : cur;
                const float c0 = 0.2f * cur.x, c1 = 0.2f * cur.y;
                const float c2 = 0.2f * cur.z, c3 = 0.2f * cur.w;
                float vp0 = fmaf(vchain, 0.8f, c0);
                vchain = (vp0 >= 1.0f) ? 0.0f : vp0;
                float vp1 = fmaf(vchain, 0.8f, c1);
                vchain = (vp1 >= 1.0f) ? 0.0f : vp1;
                float vp2 = fmaf(vchain, 0.8f, c2);
                vchain = (vp2 >= 1.0f) ? 0.0f : vp2;
                float vp3 = fmaf(vchain, 0.8f, c3);
                vchain = (vp3 >= 1.0f) ? 0.0f : vp3;
                *(float4*)(vr + 4 * q) = make_float4(vp0, vp1, vp2, vp3);
                cur = nxt;
            }
        } else if (tid < 96) {
            // ---------------- conv ----------------
            const int p = tid - 32;
            if (T + 1 < NTILES) {
                const int base = (T + 1) * TILE - 15;   // >= 49, valid
                {
                    float val = xb[base + p];
                    xs[p] = val;
                    if (p >= 1) xsh[p - 1] = val;
                }
                if (p < 15) {
                    int idx = 64 + p;
                    float val = xb[base + idx];
                    xs[idx] = val;
                    xsh[idx - 1] = val;
                }
                asm volatile("bar.sync 1, 64;" ::: "memory");
                conv_do(qh, xs, xsh, w2, bias2,
                        Ibuf + ((T + 1) & 1) * TSZ + f_loc * RS);
            }
        } else {
            // ---------------- flush ----------------
            const int ft = tid - 96;                 // 0..31
            const int r0 = ft >> 4, tq = ft & 15;    // 16 col-quads = 64 cols
            const float* ib  = Ibuf + buf * TSZ;
            const float* vpb = tvp + (buf ^ 1) * TSZ;
            const size_t tcol = (size_t)T * TILE + tq * 4;
            const size_t pcol = (size_t)(T - 1) * TILE + tq * 4;
            float4 mx = make_float4(-1e30f, -1e30f, -1e30f, -1e30f);
#pragma unroll
            for (int i = 0; i < 16; ++i) {
                const int r = r0 + 2 * i;            // rows 0..31
                const size_t grow = (size_t)(frow0 + r) * LL;
                float4 iq = *(const float4*)(ib + r * RS + tq * 4);
                stcs4(I_out + grow + tcol, iq);
                if (T >= 1) {
                    float4 vq = *(const float4*)(vpb + r * RS + tq * 4);
                    float4 sq, vn;
                    sq.x = (vq.x >= 1.0f) ? 1.0f : 0.0f;
                    sq.y = (vq.y >= 1.0f) ? 1.0f : 0.0f;
                    sq.z = (vq.z >= 1.0f) ? 1.0f : 0.0f;
                    sq.w = (vq.w >= 1.0f) ? 1.0f : 0.0f;
                    vn.x = (vq.x >= 1.0f) ? 0.0f : vq.x;
                    vn.y = (vq.y >= 1.0f) ? 0.0f : vq.y;
                    vn.z = (vq.z >= 1.0f) ? 0.0f : vq.z;
                    vn.w = (vq.w >= 1.0f) ? 0.0f : vq.w;
                    stcs4(vpre_out + grow + pcol, vq);
                    stcs4(v_out    + grow + pcol, vn);
                    stcs4(s_out    + grow + pcol, sq);
                    mx = max4(mx, vq);
                }
            }
            if (T >= 1) {
                *(float4*)(red + ft * 4) = mx;
                __syncwarp();
                if (ft < 16) {
                    float4 a  = *(float4*)(red + ft * 4);
                    float4 b4 = *(float4*)(red + (16 + ft) * 4);
                    a = max4(a, b4);
                    *(float4*)(prow + (size_t)(T - 1) * TILE + ft * 4) = a;
                }
            }
        }
        __syncthreads();
    }

    // ---- epilogue: flush v_pre/v/s + logits of tile 127 (buffer 1) ----
    if (tid >= 96) {
        const int ft = tid - 96;
        const int r0 = ft >> 4, tq = ft & 15;
        const float* vpb = tvp + ((NTILES - 1) & 1) * TSZ;
        const size_t pcol = (size_t)(NTILES - 1) * TILE + tq * 4;
        float4 mx = make_float4(-1e30f, -1e30f, -1e30f, -1e30f);
#pragma unroll
        for (int i = 0; i < 16; ++i) {
            const int r = r0 + 2 * i;
            const size_t grow = (size_t)(frow0 + r) * LL;
            float4 vq = *(const float4*)(vpb + r * RS + tq * 4);
            float4 sq, vn;
            sq.x = (vq.x >= 1.0f) ? 1.0f : 0.0f;
            sq.y = (vq.y >= 1.0f) ? 1.0f : 0.0f;
            sq.z = (vq.z >= 1.0f) ? 1.0f : 0.0f;
            sq.w = (vq.w >= 1.0f) ? 1.0f : 0.0f;
            vn.x = (vq.x >= 1.0f) ? 0.0f : vq.x;
            vn.y = (vq.y >= 1.0f) ? 0.0f : vq.y;
            vn.z = (vq.z >= 1.0f) ? 0.0f : vq.z;
            vn.w = (vq.w >= 1.0f) ? 0.0f : vq.w;
            stcs4(vpre_out + grow + pcol, vq);
            stcs4(v_out    + grow + pcol, vn);
            stcs4(s_out    + grow + pcol, sq);
            mx = max4(mx, vq);
        }
        *(float4*)(red + ft * 4) = mx;
        __syncwarp();
        if (ft < 16) {
            float4 a  = *(float4*)(red + ft * 4);
            float4 b4 = *(float4*)(red + (16 + ft) * 4);
            a = max4(a, b4);
            *(float4*)(prow + (size_t)(NTILES - 1) * TILE + ft * 4) = a;
        }
    }
}

// ---------------------------------------------------------------------------
// Combine the four filter-quarter partial maxes into logits (float4).
// ---------------------------------------------------------------------------
__global__ __launch_bounds__(256) void logits_kernel(float* __restrict__ logits)
{
    int i = blockIdx.x * blockDim.x + threadIdx.x;   // 0 .. BB*LL/4-1
    int b = i >> 11;                                 // 2048 float4 per batch
    int l4 = i & 2047;
    const float4* p0 = (const float4*)(g_partial + (size_t)(4 * b)     * LL) + l4;
    const float4* p1 = (const float4*)(g_partial + (size_t)(4 * b + 1) * LL) + l4;
    const float4* p2 = (const float4*)(g_partial + (size_t)(4 * b + 2) * LL) + l4;
    const float4* p3 = (const float4*)(g_partial + (size_t)(4 * b + 3) * LL) + l4;
    float4 m = max4(max4(*p0, *p1), max4(*p2, *p3));
    m.x -= 1.0f; m.y -= 1.0f; m.z -= 1.0f; m.w -= 1.0f;
    stcs4(logits + (size_t)b * LL + l4 * 4, m);
}

extern "C" void kernel_launch(void* const* d_in, const int* in_sizes, int n_in,
                              void* d_out, int out_size)
{
    const float* x    = (const float*)d_in[0];
    const float* W    = (const float*)d_in[1];
    const float* bias = (const float*)d_in[2];
    float* out = (float*)d_out;

    const size_t N = (size_t)BB * FF * LL;   // 67,108,864
    float* I    = out;
    float* vpre = out + N;
    float* vv   = out + 2 * N;
    float* ss   = out + 3 * N;
    float* lg   = out + 4 * N;

    const int smem_bytes = (4 * TSZ + 84 + 84 + 128) * sizeof(float); // ~36KB
    cudaFuncSetAttribute(snn_fused,
                         cudaFuncAttributeMaxDynamicSharedMemorySize, smem_bytes);

    snn_fused<<<256, 128, smem_bytes>>>(x, W, bias, I, vpre, vv, ss);
    logits_kernel<<<(BB * LL / 4) / 256, 256>>>(lg);
}

// round 9
// speedup vs baseline: 1.2592x; 1.0138x over previous
#include <cuda_runtime.h>

#define BB 64
#define FF 128
#define LL 8192
#define KK 16
#define TILE 128
#define NTILES (LL / TILE)      // 64
#define RS 132                  // padded SMEM row stride (floats)
#define TSZ (64 * RS)           // 8448 floats per tile buffer

typedef unsigned long long u64;

__device__ float g_partial[128 * LL];   // per-(batch,half) partial logits max
__device__ u64   g_ctr;                 // grid retirement ticket (monotone)

__device__ __forceinline__ u64 fma2(u64 a, u64 b, u64 c) {
    u64 d;
    asm("fma.rn.f32x2 %0, %1, %2, %3;" : "=l"(d) : "l"(a), "l"(b), "l"(c));
    return d;
}
__device__ __forceinline__ u64 pack2(float lo, float hi) {
    u64 d; asm("mov.b64 %0, {%1, %2};" : "=l"(d) : "f"(lo), "f"(hi)); return d;
}
__device__ __forceinline__ void unpack2(u64 v, float& lo, float& hi) {
    asm("mov.b64 {%0, %1}, %2;" : "=f"(lo), "=f"(hi) : "l"(v));
}
__device__ __forceinline__ void stcs4(float* p, float4 v) {
    asm volatile("st.global.cs.v4.f32 [%0], {%1,%2,%3,%4};"
                 :: "l"(p), "f"(v.x), "f"(v.y), "f"(v.z), "f"(v.w) : "memory");
}
__device__ __forceinline__ float4 max4(float4 a, float4 b) {
    return make_float4(fmaxf(a.x, b.x), fmaxf(a.y, b.y),
                       fmaxf(a.z, b.z), fmaxf(a.w, b.w));
}

// ---------------------------------------------------------------------------
// conv: one column half (16 quads, 64 cols) for fixed filter f. f32x2 FMAs.
// xs[p] = x[tile*128 - 15 + p]; xsh[q] = xs[q+1] (odd-parity pairs).
// ---------------------------------------------------------------------------
__device__ __forceinline__ void conv_do(
    int qh, const float* __restrict__ xs, const float* __restrict__ xsh,
    const u64* __restrict__ w2, u64 bias2, float* __restrict__ irow)
{
#pragma unroll
    for (int j = 0; j < 16; ++j) {
        const int lt4 = qh * 64 + 4 * j;     // even
        u64 P[18];
#pragma unroll
        for (int m = 0; m < 18; ++m) {
            int base = lt4 + m;              // parity == m parity
            P[m] = (m & 1) ? *(const u64*)(xsh + (base - 1))
                           : *(const u64*)(xs + base);
        }
        u64 a01 = bias2, a23 = bias2;
#pragma unroll
        for (int k = 0; k < KK; ++k) {
            a01 = fma2(w2[k], P[k],     a01);
            a23 = fma2(w2[k], P[k + 2], a23);
        }
        float o0, o1, o2, o3;
        unpack2(a01, o0, o1);
        unpack2(a23, o2, o3);
        *(float4*)(irow + lt4) = make_float4(o0, o1, o2, o3);
    }
}

// ---------------------------------------------------------------------------
// Fused conv + LIF + coalesced streaming stores + fused logits partial max,
// then a grid-wide retirement epilogue combines partials into final logits.
// Grid 128 = (batch, filter-half) — all blocks co-resident (1/SM), so the
// retirement spin is deadlock-free. 256 threads:
//   tid   0- 63 : chain warps  — LIF recurrence -> v_pre tiles in SMEM
//   tid  64-191 : conv warps   — f32x2 conv of tile T+1 (double-buffered)
//   tid 192-255 : flush warps  — STG I(T); STG v_pre/v/s(T-1) with derive;
//                                column-max -> g_partial
// ---------------------------------------------------------------------------
__global__ __launch_bounds__(256, 1) void snn_fused(
    const float* __restrict__ x, const float* __restrict__ W,
    const float* __restrict__ bias,
    float* __restrict__ I_out, float* __restrict__ vpre_out,
    float* __restrict__ v_out, float* __restrict__ s_out,
    float* __restrict__ logits)
{
    extern __shared__ float sm[];
    float* Ibuf = sm;                 // 2*TSZ
    float* tvp  = sm + 2 * TSZ;       // 2*TSZ
    float* xs   = sm + 4 * TSZ;       // 144 (143 used)
    float* xsh  = xs + 144;           // 144
    float* red  = xsh + 144;          // 256

    const int tid   = threadIdx.x;
    const int b     = blockIdx.x >> 1;
    const int h     = blockIdx.x & 1;
    const int frow0 = b * FF + h * 64;          // OUTPUT row base
    const float* __restrict__ xb = x + (size_t)b * LL;
    float* __restrict__ prow = g_partial + (size_t)blockIdx.x * LL;

    // conv-thread persistent state (filter index is batch-INDEPENDENT)
    u64 w2[KK];
    u64 bias2 = 0;
    int f_loc = 0, qh = 0;
    if (tid >= 64 && tid < 192) {
        const int p = tid - 64;
        f_loc = p >> 1; qh = p & 1;
        const int fflt = h * 64 + f_loc;        // filter index 0..127
#pragma unroll
        for (int k = 0; k < KK; ++k) {
            const float w = W[fflt * KK + k];
            w2[k] = pack2(w, w);
        }
        const float bv = bias[fflt];
        bias2 = pack2(bv, bv);
    }

    // ---- prologue: stage xs(tile0), conv tile0 -> Ibuf[0] ----
    if (tid >= 64 && tid < 192) {
        const int p = tid - 64;
        {
            int g = p - 15;
            float val = (g >= 0) ? xb[g] : 0.0f;
            xs[p] = val;
            if (p >= 1) xsh[p - 1] = val;
        }
        if (p < 15) {
            int idx = 128 + p;
            float val = xb[idx - 15];
            xs[idx] = val;
            xsh[idx - 1] = val;
        }
        asm volatile("bar.sync 1, 128;" ::: "memory");
        conv_do(qh, xs, xsh, w2, bias2, Ibuf + f_loc * RS);
    }
    __syncthreads();

    float vchain = 0.0f;

    for (int T = 0; T < NTILES; ++T) {
        const int buf = T & 1;
        if (tid < 64) {
            // ---------------- chain ----------------
            const float* ir = Ibuf + buf * TSZ + tid * RS;
            float* vr = tvp + buf * TSZ + tid * RS;
            float4 cur = *(const float4*)ir;
#pragma unroll
            for (int q = 0; q < 32; ++q) {
                float4 nxt = (q < 31) ? *(const float4*)(ir + 4 * (q + 1)) : cur;
                const float c0 = 0.2f * cur.x, c1 = 0.2f * cur.y;
                const float c2 = 0.2f * cur.z, c3 = 0.2f * cur.w;
                float vp0 = fmaf(vchain, 0.8f, c0);
                vchain = (vp0 >= 1.0f) ? 0.0f : vp0;
                float vp1 = fmaf(vchain, 0.8f, c1);
                vchain = (vp1 >= 1.0f) ? 0.0f : vp1;
                float vp2 = fmaf(vchain, 0.8f, c2);
                vchain = (vp2 >= 1.0f) ? 0.0f : vp2;
                float vp3 = fmaf(vchain, 0.8f, c3);
                vchain = (vp3 >= 1.0f) ? 0.0f : vp3;
                *(float4*)(vr + 4 * q) = make_float4(vp0, vp1, vp2, vp3);
                cur = nxt;
            }
        } else if (tid < 192) {
            // ---------------- conv ----------------
            const int p = tid - 64;
            if (T + 1 < NTILES) {
                {
                    int g = (T + 1) * TILE - 15 + p;   // >= 113, valid
                    float val = xb[g];
                    xs[p] = val;
                    if (p >= 1) xsh[p - 1] = val;
                }
                if (p < 15) {
                    int idx = 128 + p;
                    float val = xb[(T + 1) * TILE - 15 + idx];
                    xs[idx] = val;
                    xsh[idx - 1] = val;
                }
                asm volatile("bar.sync 1, 128;" ::: "memory");
                conv_do(qh, xs, xsh, w2, bias2,
                        Ibuf + ((T + 1) & 1) * TSZ + f_loc * RS);
            }
        } else {
            // ---------------- flush ----------------
            const int ft = tid - 192;
            const int r0 = ft >> 5, tq = ft & 31;    // warp covers full rows
            const float* ib  = Ibuf + buf * TSZ;
            const float* vpb = tvp + (buf ^ 1) * TSZ;
            const size_t tcol = (size_t)T * TILE + tq * 4;
            const size_t pcol = (size_t)(T - 1) * TILE + tq * 4;
            float4 mx = make_float4(-1e30f, -1e30f, -1e30f, -1e30f);
#pragma unroll
            for (int i = 0; i < 32; ++i) {
                const int r = r0 + 2 * i;
                const size_t grow = (size_t)(frow0 + r) * LL;
                float4 iq = *(const float4*)(ib + r * RS + tq * 4);
                stcs4(I_out + grow + tcol, iq);
                if (T >= 1) {
                    float4 vq = *(const float4*)(vpb + r * RS + tq * 4);
                    float4 sq, vn;
                    sq.x = (vq.x >= 1.0f) ? 1.0f : 0.0f;
                    sq.y = (vq.y >= 1.0f) ? 1.0f : 0.0f;
                    sq.z = (vq.z >= 1.0f) ? 1.0f : 0.0f;
                    sq.w = (vq.w >= 1.0f) ? 1.0f : 0.0f;
                    vn.x = (vq.x >= 1.0f) ? 0.0f : vq.x;
                    vn.y = (vq.y >= 1.0f) ? 0.0f : vq.y;
                    vn.z = (vq.z >= 1.0f) ? 0.0f : vq.z;
                    vn.w = (vq.w >= 1.0f) ? 0.0f : vq.w;
                    stcs4(vpre_out + grow + pcol, vq);
                    stcs4(v_out    + grow + pcol, vn);
                    stcs4(s_out    + grow + pcol, sq);
                    mx = max4(mx, vq);
                }
            }
            if (T >= 1) {
                *(float4*)(red + ft * 4) = mx;
                asm volatile("bar.sync 3, 64;" ::: "memory");
                if (ft < 32) {
                    float4 a  = *(float4*)(red + ft * 4);
                    float4 b4 = *(float4*)(red + (32 + ft) * 4);
                    a = max4(a, b4);
                    *(float4*)(prow + (size_t)(T - 1) * TILE + ft * 4) = a;
                }
            }
        }
        __syncthreads();
    }

    // ---- epilogue: flush v_pre/v/s + partial max of tile 63 (buffer 1) ----
    if (tid >= 192) {
        const int ft = tid - 192;
        const int r0 = ft >> 5, tq = ft & 31;
        const float* vpb = tvp + ((NTILES - 1) & 1) * TSZ;
        const size_t pcol = (size_t)(NTILES - 1) * TILE + tq * 4;
        float4 mx = make_float4(-1e30f, -1e30f, -1e30f, -1e30f);
#pragma unroll
        for (int i = 0; i < 32; ++i) {
            const int r = r0 + 2 * i;
            const size_t grow = (size_t)(frow0 + r) * LL;
            float4 vq = *(const float4*)(vpb + r * RS + tq * 4);
            float4 sq, vn;
            sq.x = (vq.x >= 1.0f) ? 1.0f : 0.0f;
            sq.y = (vq.y >= 1.0f) ? 1.0f : 0.0f;
            sq.z = (vq.z >= 1.0f) ? 1.0f : 0.0f;
            sq.w = (vq.w >= 1.0f) ? 1.0f : 0.0f;
            vn.x = (vq.x >= 1.0f) ? 0.0f : vq.x;
            vn.y = (vq.y >= 1.0f) ? 0.0f : vq.y;
            vn.z = (vq.z >= 1.0f) ? 0.0f : vq.z;
            vn.w = (vq.w >= 1.0f) ? 0.0f : vq.w;
            stcs4(vpre_out + grow + pcol, vq);
            stcs4(v_out    + grow + pcol, vn);
            stcs4(s_out    + grow + pcol, sq);
            mx = max4(mx, vq);
        }
        *(float4*)(red + ft * 4) = mx;
        asm volatile("bar.sync 3, 64;" ::: "memory");
        if (ft < 32) {
            float4 a  = *(float4*)(red + ft * 4);
            float4 b4 = *(float4*)(red + (32 + ft) * 4);
            a = max4(a, b4);
            *(float4*)(prow + (size_t)(NTILES - 1) * TILE + ft * 4) = a;
        }
    }

    // ---- grid-wide retirement: combine partials into final logits ----
    // All 128 blocks are co-resident (1 block/SM), so spinning is safe.
    // Ticket math is replay-safe: target = first multiple of 128 above ticket.
    __syncthreads();
    __threadfence();
    __shared__ u64 s_tgt;
    if (tid == 0) {
        u64 t = atomicAdd(&g_ctr, 1ULL);
        s_tgt = (t - (t & 127ULL)) + 128ULL;
    }
    __syncthreads();
    if (tid == 0) {
        const u64 tgt = s_tgt;
        for (;;) {
            u64 v;
            asm volatile("ld.global.acquire.gpu.u64 %0, [%1];"
                         : "=l"(v) : "l"(&g_ctr));
            if (v >= tgt) break;
            __nanosleep(64);
        }
    }
    __syncthreads();
    __threadfence();

    {
        // block (2b+h) combines logits for batch b over L-half h (4096 cols)
        const size_t off = (size_t)h * 4096;
        const float4* q0 = (const float4*)(g_partial + (size_t)(2 * b) * LL + off);
        const float4* q1 = (const float4*)(g_partial + (size_t)(2 * b + 1) * LL + off);
        float* lgp = logits + (size_t)b * LL + off;
#pragma unroll
        for (int k = 0; k < 4; ++k) {
            const int idx = tid + k * 256;          // 0..1023 float4
            float4 m = max4(q0[idx], q1[idx]);
            m.x -= 1.0f; m.y -= 1.0f; m.z -= 1.0f; m.w -= 1.0f;
            stcs4(lgp + idx * 4, m);
        }
    }
}

extern "C" void kernel_launch(void* const* d_in, const int* in_sizes, int n_in,
                              void* d_out, int out_size)
{
    const float* x    = (const float*)d_in[0];
    const float* W    = (const float*)d_in[1];
    const float* bias = (const float*)d_in[2];
    float* out = (float*)d_out;

    const size_t N = (size_t)BB * FF * LL;   // 67,108,864
    float* I    = out;
    float* vpre = out + N;
    float* vv   = out + 2 * N;
    float* ss   = out + 3 * N;
    float* lg   = out + 4 * N;

    const int smem_bytes = (4 * TSZ + 144 + 144 + 256) * sizeof(float); // ~137.4KB
    cudaFuncSetAttribute(snn_fused,
                         cudaFuncAttributeMaxDynamicSharedMemorySize, smem_bytes);

    snn_fused<<<128, 256, smem_bytes>>>(x, W, bias, I, vpre, vv, ss, lg);
}

// round 10
// speedup vs baseline: 1.2594x; 1.0002x over previous
#include <cuda_runtime.h>

#define BB 64
#define FF 128
#define LL 8192
#define KK 16
#define TILE 128
#define NTILES (LL / TILE)      // 64
#define RS 132                  // padded SMEM row stride (floats)
#define TSZ (64 * RS)           // 8448 floats per tile buffer

typedef unsigned long long u64;

__device__ float g_partial[128 * LL];   // per-(batch,half) partial logits max
__device__ unsigned int g_pairctr[BB];  // per-batch arrival tickets (monotone)

__device__ __forceinline__ u64 fma2(u64 a, u64 b, u64 c) {
    u64 d;
    asm("fma.rn.f32x2 %0, %1, %2, %3;" : "=l"(d) : "l"(a), "l"(b), "l"(c));
    return d;
}
__device__ __forceinline__ u64 pack2(float lo, float hi) {
    u64 d; asm("mov.b64 %0, {%1, %2};" : "=l"(d) : "f"(lo), "f"(hi)); return d;
}
__device__ __forceinline__ void unpack2(u64 v, float& lo, float& hi) {
    asm("mov.b64 {%0, %1}, %2;" : "=f"(lo), "=f"(hi) : "l"(v));
}
__device__ __forceinline__ void stcs4(float* p, float4 v) {
    asm volatile("st.global.cs.v4.f32 [%0], {%1,%2,%3,%4};"
                 :: "l"(p), "f"(v.x), "f"(v.y), "f"(v.z), "f"(v.w) : "memory");
}
__device__ __forceinline__ float4 max4(float4 a, float4 b) {
    return make_float4(fmaxf(a.x, b.x), fmaxf(a.y, b.y),
                       fmaxf(a.z, b.z), fmaxf(a.w, b.w));
}

// ---------------------------------------------------------------------------
// conv: one column half (16 quads, 64 cols) for fixed filter f. f32x2 FMAs.
// xs[p] = x[tile*128 - 15 + p]; xsh[q] = xs[q+1] (odd-parity pairs).
// ---------------------------------------------------------------------------
__device__ __forceinline__ void conv_do(
    int qh, const float* __restrict__ xs, const float* __restrict__ xsh,
    const u64* __restrict__ w2, u64 bias2, float* __restrict__ irow)
{
#pragma unroll
    for (int j = 0; j < 16; ++j) {
        const int lt4 = qh * 64 + 4 * j;     // even
        u64 P[18];
#pragma unroll
        for (int m = 0; m < 18; ++m) {
            int base = lt4 + m;              // parity == m parity
            P[m] = (m & 1) ? *(const u64*)(xsh + (base - 1))
                           : *(const u64*)(xs + base);
        }
        u64 a01 = bias2, a23 = bias2;
#pragma unroll
        for (int k = 0; k < KK; ++k) {
            a01 = fma2(w2[k], P[k],     a01);
            a23 = fma2(w2[k], P[k + 2], a23);
        }
        float o0, o1, o2, o3;
        unpack2(a01, o0, o1);
        unpack2(a23, o2, o3);
        *(float4*)(irow + lt4) = make_float4(o0, o1, o2, o3);
    }
}

// ---------------------------------------------------------------------------
// Fused conv + LIF + coalesced streaming stores + fused logits partial max,
// with PAIRWISE retirement: the 2nd-finishing block of each (batch) pair
// combines the two half-maxes into final logits. No grid-wide sync.
// Grid 128 = (batch, filter-half), 256 threads:
//   tid   0- 63 : chain warps  — LIF recurrence -> v_pre tiles in SMEM
//   tid  64-191 : conv warps   — f32x2 conv of tile T+1 (double-buffered)
//   tid 192-255 : flush warps  — STG I(T); STG v_pre/v/s(T-1) with derive;
//                                column-max -> g_partial
// ---------------------------------------------------------------------------
__global__ __launch_bounds__(256, 1) void snn_fused(
    const float* __restrict__ x, const float* __restrict__ W,
    const float* __restrict__ bias,
    float* __restrict__ I_out, float* __restrict__ vpre_out,
    float* __restrict__ v_out, float* __restrict__ s_out,
    float* __restrict__ logits)
{
    extern __shared__ float sm[];
    float* Ibuf = sm;                 // 2*TSZ
    float* tvp  = sm + 2 * TSZ;       // 2*TSZ
    float* xs   = sm + 4 * TSZ;       // 144 (143 used)
    float* xsh  = xs + 144;           // 144
    float* red  = xsh + 144;          // 256

    const int tid   = threadIdx.x;
    const int b     = blockIdx.x >> 1;
    const int h     = blockIdx.x & 1;
    const int frow0 = b * FF + h * 64;          // OUTPUT row base
    const float* __restrict__ xb = x + (size_t)b * LL;
    float* __restrict__ prow = g_partial + (size_t)blockIdx.x * LL;

    // conv-thread persistent state (filter index is batch-INDEPENDENT)
    u64 w2[KK];
    u64 bias2 = 0;
    int f_loc = 0, qh = 0;
    if (tid >= 64 && tid < 192) {
        const int p = tid - 64;
        f_loc = p >> 1; qh = p & 1;
        const int fflt = h * 64 + f_loc;        // filter index 0..127
#pragma unroll
        for (int k = 0; k < KK; ++k) {
            const float w = W[fflt * KK + k];
            w2[k] = pack2(w, w);
        }
        const float bv = bias[fflt];
        bias2 = pack2(bv, bv);
    }

    // ---- prologue: stage xs(tile0), conv tile0 -> Ibuf[0] ----
    if (tid >= 64 && tid < 192) {
        const int p = tid - 64;
        {
            int g = p - 15;
            float val = (g >= 0) ? xb[g] : 0.0f;
            xs[p] = val;
            if (p >= 1) xsh[p - 1] = val;
        }
        if (p < 15) {
            int idx = 128 + p;
            float val = xb[idx - 15];
            xs[idx] = val;
            xsh[idx - 1] = val;
        }
        asm volatile("bar.sync 1, 128;" ::: "memory");
        conv_do(qh, xs, xsh, w2, bias2, Ibuf + f_loc * RS);
    }
    __syncthreads();

    float vchain = 0.0f;

    for (int T = 0; T < NTILES; ++T) {
        const int buf = T & 1;
        if (tid < 64) {
            // ---------------- chain ----------------
            const float* ir = Ibuf + buf * TSZ + tid * RS;
            float* vr = tvp + buf * TSZ + tid * RS;
            float4 cur = *(const float4*)ir;
#pragma unroll
            for (int q = 0; q < 32; ++q) {
                float4 nxt = (q < 31) ? *(const float4*)(ir + 4 * (q + 1)) : cur;
                const float c0 = 0.2f * cur.x, c1 = 0.2f * cur.y;
                const float c2 = 0.2f * cur.z, c3 = 0.2f * cur.w;
                float vp0 = fmaf(vchain, 0.8f, c0);
                vchain = (vp0 >= 1.0f) ? 0.0f : vp0;
                float vp1 = fmaf(vchain, 0.8f, c1);
                vchain = (vp1 >= 1.0f) ? 0.0f : vp1;
                float vp2 = fmaf(vchain, 0.8f, c2);
                vchain = (vp2 >= 1.0f) ? 0.0f : vp2;
                float vp3 = fmaf(vchain, 0.8f, c3);
                vchain = (vp3 >= 1.0f) ? 0.0f : vp3;
                *(float4*)(vr + 4 * q) = make_float4(vp0, vp1, vp2, vp3);
                cur = nxt;
            }
        } else if (tid < 192) {
            // ---------------- conv ----------------
            const int p = tid - 64;
            if (T + 1 < NTILES) {
                {
                    int g = (T + 1) * TILE - 15 + p;   // >= 113, valid
                    float val = xb[g];
                    xs[p] = val;
                    if (p >= 1) xsh[p - 1] = val;
                }
                if (p < 15) {
                    int idx = 128 + p;
                    float val = xb[(T + 1) * TILE - 15 + idx];
                    xs[idx] = val;
                    xsh[idx - 1] = val;
                }
                asm volatile("bar.sync 1, 128;" ::: "memory");
                conv_do(qh, xs, xsh, w2, bias2,
                        Ibuf + ((T + 1) & 1) * TSZ + f_loc * RS);
            }
        } else {
            // ---------------- flush ----------------
            const int ft = tid - 192;
            const int r0 = ft >> 5, tq = ft & 31;    // warp covers full rows
            const float* ib  = Ibuf + buf * TSZ;
            const float* vpb = tvp + (buf ^ 1) * TSZ;
            const size_t tcol = (size_t)T * TILE + tq * 4;
            const size_t pcol = (size_t)(T - 1) * TILE + tq * 4;
            float4 mx = make_float4(-1e30f, -1e30f, -1e30f, -1e30f);
#pragma unroll
            for (int i = 0; i < 32; ++i) {
                const int r = r0 + 2 * i;
                const size_t grow = (size_t)(frow0 + r) * LL;
                float4 iq = *(const float4*)(ib + r * RS + tq * 4);
                stcs4(I_out + grow + tcol, iq);
                if (T >= 1) {
                    float4 vq = *(const float4*)(vpb + r * RS + tq * 4);
                    float4 sq, vn;
                    sq.x = (vq.x >= 1.0f) ? 1.0f : 0.0f;
                    sq.y = (vq.y >= 1.0f) ? 1.0f : 0.0f;
                    sq.z = (vq.z >= 1.0f) ? 1.0f : 0.0f;
                    sq.w = (vq.w >= 1.0f) ? 1.0f : 0.0f;
                    vn.x = (vq.x >= 1.0f) ? 0.0f : vq.x;
                    vn.y = (vq.y >= 1.0f) ? 0.0f : vq.y;
                    vn.z = (vq.z >= 1.0f) ? 0.0f : vq.z;
                    vn.w = (vq.w >= 1.0f) ? 0.0f : vq.w;
                    stcs4(vpre_out + grow + pcol, vq);
                    stcs4(v_out    + grow + pcol, vn);
                    stcs4(s_out    + grow + pcol, sq);
                    mx = max4(mx, vq);
                }
            }
            if (T >= 1) {
                *(float4*)(red + ft * 4) = mx;
                asm volatile("bar.sync 3, 64;" ::: "memory");
                if (ft < 32) {
                    float4 a  = *(float4*)(red + ft * 4);
                    float4 b4 = *(float4*)(red + (32 + ft) * 4);
                    a = max4(a, b4);
                    *(float4*)(prow + (size_t)(T - 1) * TILE + ft * 4) = a;
                }
            }
        }
        __syncthreads();
    }

    // ---- epilogue: flush v_pre/v/s + partial max of tile 63 (buffer 1) ----
    if (tid >= 192) {
        const int ft = tid - 192;
        const int r0 = ft >> 5, tq = ft & 31;
        const float* vpb = tvp + ((NTILES - 1) & 1) * TSZ;
        const size_t pcol = (size_t)(NTILES - 1) * TILE + tq * 4;
        float4 mx = make_float4(-1e30f, -1e30f, -1e30f, -1e30f);
#pragma unroll
        for (int i = 0; i < 32; ++i) {
            const int r = r0 + 2 * i;
            const size_t grow = (size_t)(frow0 + r) * LL;
            float4 vq = *(const float4*)(vpb + r * RS + tq * 4);
            float4 sq, vn;
            sq.x = (vq.x >= 1.0f) ? 1.0f : 0.0f;
            sq.y = (vq.y >= 1.0f) ? 1.0f : 0.0f;
            sq.z = (vq.z >= 1.0f) ? 1.0f : 0.0f;
            sq.w = (vq.w >= 1.0f) ? 1.0f : 0.0f;
            vn.x = (vq.x >= 1.0f) ? 0.0f : vq.x;
            vn.y = (vq.y >= 1.0f) ? 0.0f : vq.y;
            vn.z = (vq.z >= 1.0f) ? 0.0f : vq.z;
            vn.w = (vq.w >= 1.0f) ? 0.0f : vq.w;
            stcs4(vpre_out + grow + pcol, vq);
            stcs4(v_out    + grow + pcol, vn);
            stcs4(s_out    + grow + pcol, sq);
            mx = max4(mx, vq);
        }
        *(float4*)(red + ft * 4) = mx;
        asm volatile("bar.sync 3, 64;" ::: "memory");
        if (ft < 32) {
            float4 a  = *(float4*)(red + ft * 4);
            float4 b4 = *(float4*)(red + (32 + ft) * 4);
            a = max4(a, b4);
            *(float4*)(prow + (size_t)(NTILES - 1) * TILE + ft * 4) = a;
        }
    }

    // ---- pairwise retirement: 2nd-arriving block of pair combines logits ----
    // Counter is monotone (never reset): exactly 2 increments per pair per
    // replay, so "odd old value" == "I am second this replay". Release:
    // bar.sync orders all threads' partial writes before tid0's fence+atomic.
    __syncthreads();
    __shared__ int s_second;
    if (tid == 0) {
        __threadfence();
        unsigned int old = atomicAdd(&g_pairctr[b], 1u);
        s_second = (int)(old & 1u);
        if (s_second) __threadfence();   // acquire: peer partials now visible
    }
    __syncthreads();
    if (s_second) {
        const float4* q0 = (const float4*)(g_partial + (size_t)(2 * b) * LL);
        const float4* q1 = (const float4*)(g_partial + (size_t)(2 * b + 1) * LL);
        float* lgp = logits + (size_t)b * LL;
#pragma unroll
        for (int k = 0; k < 8; ++k) {
            const int idx = tid + k * 256;          // 0..2047 float4
            float4 m = max4(q0[idx], q1[idx]);
            m.x -= 1.0f; m.y -= 1.0f; m.z -= 1.0f; m.w -= 1.0f;
            stcs4(lgp + idx * 4, m);
        }
    }
}

extern "C" void kernel_launch(void* const* d_in, const int* in_sizes, int n_in,
                              void* d_out, int out_size)
{
    const float* x    = (const float*)d_in[0];
    const float* W    = (const float*)d_in[1];
    const float* bias = (const float*)d_in[2];
    float* out = (float*)d_out;

    const size_t N = (size_t)BB * FF * LL;   // 67,108,864
    float* I    = out;
    float* vpre = out + N;
    float* vv   = out + 2 * N;
    float* ss   = out + 3 * N;
    float* lg   = out + 4 * N;

    const int smem_bytes = (4 * TSZ + 144 + 144 + 256) * sizeof(float); // ~137.4KB
    cudaFuncSetAttribute(snn_fused,
                         cudaFuncAttributeMaxDynamicSharedMemorySize, smem_bytes);

    snn_fused<<<128, 256, smem_bytes>>>(x, W, bias, I, vpre, vv, ss, lg);
}

// round 11
// speedup vs baseline: 1.2734x; 1.0111x over previous
#include <cuda_runtime.h>

#define BB 64
#define FF 128
#define LL 8192
#define KK 16
#define TILE 128
#define NTILES (LL / TILE)      // 64
#define RS 132                  // padded SMEM row stride (floats)
#define TSZ (64 * RS)           // 8448 floats per tile buffer

typedef unsigned long long u64;

__device__ float g_partial[128 * LL];   // per-(batch,half) partial logits max

__device__ __forceinline__ u64 fma2(u64 a, u64 b, u64 c) {
    u64 d;
    asm("fma.rn.f32x2 %0, %1, %2, %3;" : "=l"(d) : "l"(a), "l"(b), "l"(c));
    return d;
}
__device__ __forceinline__ u64 pack2(float lo, float hi) {
    u64 d; asm("mov.b64 %0, {%1, %2};" : "=l"(d) : "f"(lo), "f"(hi)); return d;
}
__device__ __forceinline__ void unpack2(u64 v, float& lo, float& hi) {
    asm("mov.b64 {%0, %1}, %2;" : "=f"(lo), "=f"(hi) : "l"(v));
}
__device__ __forceinline__ void stcs4(float* p, float4 v) {
    asm volatile("st.global.cs.v4.f32 [%0], {%1,%2,%3,%4};"
                 :: "l"(p), "f"(v.x), "f"(v.y), "f"(v.z), "f"(v.w) : "memory");
}
__device__ __forceinline__ float4 max4(float4 a, float4 b) {
    return make_float4(fmaxf(a.x, b.x), fmaxf(a.y, b.y),
                       fmaxf(a.z, b.z), fmaxf(a.w, b.w));
}

// ---------------------------------------------------------------------------
// conv: one column half (16 quads, 64 cols) for fixed filter f. f32x2 FMAs.
// xs[p] = x[tile*128 - 15 + p]; xsh[q] = xs[q+1] (odd-parity pairs).
// ---------------------------------------------------------------------------
__device__ __forceinline__ void conv_do(
    int qh, const float* __restrict__ xs, const float* __restrict__ xsh,
    const u64* __restrict__ w2, u64 bias2, float* __restrict__ irow)
{
#pragma unroll
    for (int j = 0; j < 16; ++j) {
        const int lt4 = qh * 64 + 4 * j;     // even
        u64 P[18];
#pragma unroll
        for (int m = 0; m < 18; ++m) {
            int base = lt4 + m;              // parity == m parity
            P[m] = (m & 1) ? *(const u64*)(xsh + (base - 1))
                           : *(const u64*)(xs + base);
        }
        u64 a01 = bias2, a23 = bias2;
#pragma unroll
        for (int k = 0; k < KK; ++k) {
            a01 = fma2(w2[k], P[k],     a01);
            a23 = fma2(w2[k], P[k + 2], a23);
        }
        float o0, o1, o2, o3;
        unpack2(a01, o0, o1);
        unpack2(a23, o2, o3);
        *(float4*)(irow + lt4) = make_float4(o0, o1, o2, o3);
    }
}

// ---------------------------------------------------------------------------
// Fused conv + LIF + coalesced streaming stores + fused logits partial max.
// Grid 128 = (batch, filter-half), 256 threads:
//   tid   0- 63 : chain warps  — LIF recurrence -> v_pre tiles in SMEM
//   tid  64-191 : conv warps   — f32x2 conv of tile T+1 (double-buffered)
//   tid 192-255 : flush warps  — STG I(T); STG v_pre/v/s(T-1) with derive;
//                                column-max -> g_partial
// ---------------------------------------------------------------------------
__global__ __launch_bounds__(256, 1) void snn_fused(
    const float* __restrict__ x, const float* __restrict__ W,
    const float* __restrict__ bias,
    float* __restrict__ I_out, float* __restrict__ vpre_out,
    float* __restrict__ v_out, float* __restrict__ s_out)
{
    extern __shared__ float sm[];
    float* Ibuf = sm;                 // 2*TSZ
    float* tvp  = sm + 2 * TSZ;       // 2*TSZ
    float* xs   = sm + 4 * TSZ;       // 144 (143 used)
    float* xsh  = xs + 144;           // 144
    float* red  = xsh + 144;          // 256

    const int tid   = threadIdx.x;
    const int b     = blockIdx.x >> 1;
    const int h     = blockIdx.x & 1;
    const int frow0 = b * FF + h * 64;          // OUTPUT row base
    const float* __restrict__ xb = x + (size_t)b * LL;
    float* __restrict__ prow = g_partial + (size_t)blockIdx.x * LL;

    // conv-thread persistent state (filter index is batch-INDEPENDENT)
    u64 w2[KK];
    u64 bias2 = 0;
    int f_loc = 0, qh = 0;
    if (tid >= 64 && tid < 192) {
        const int p = tid - 64;
        f_loc = p >> 1; qh = p & 1;
        const int fflt = h * 64 + f_loc;        // filter index 0..127
#pragma unroll
        for (int k = 0; k < KK; ++k) {
            const float w = W[fflt * KK + k];
            w2[k] = pack2(w, w);
        }
        const float bv = bias[fflt];
        bias2 = pack2(bv, bv);
    }

    // ---- prologue: stage xs(tile0), conv tile0 -> Ibuf[0] ----
    if (tid >= 64 && tid < 192) {
        const int p = tid - 64;
        {
            int g = p - 15;
            float val = (g >= 0) ? xb[g] : 0.0f;
            xs[p] = val;
            if (p >= 1) xsh[p - 1] = val;
        }
        if (p < 15) {
            int idx = 128 + p;
            float val = xb[idx - 15];
            xs[idx] = val;
            xsh[idx - 1] = val;
        }
        asm volatile("bar.sync 1, 128;" ::: "memory");
        conv_do(qh, xs, xsh, w2, bias2, Ibuf + f_loc * RS);
    }
    __syncthreads();

    float vchain = 0.0f;

    for (int T = 0; T < NTILES; ++T) {
        const int buf = T & 1;
        if (tid < 64) {
            // ---------------- chain ----------------
            const float* ir = Ibuf + buf * TSZ + tid * RS;
            float* vr = tvp + buf * TSZ + tid * RS;
            float4 cur = *(const float4*)ir;
#pragma unroll
            for (int q = 0; q < 32; ++q) {
                float4 nxt = (q < 31) ? *(const float4*)(ir + 4 * (q + 1)) : cur;
                const float c0 = 0.2f * cur.x, c1 = 0.2f * cur.y;
                const float c2 = 0.2f * cur.z, c3 = 0.2f * cur.w;
                float vp0 = fmaf(vchain, 0.8f, c0);
                vchain = (vp0 >= 1.0f) ? 0.0f : vp0;
                float vp1 = fmaf(vchain, 0.8f, c1);
                vchain = (vp1 >= 1.0f) ? 0.0f : vp1;
                float vp2 = fmaf(vchain, 0.8f, c2);
                vchain = (vp2 >= 1.0f) ? 0.0f : vp2;
                float vp3 = fmaf(vchain, 0.8f, c3);
                vchain = (vp3 >= 1.0f) ? 0.0f : vp3;
                *(float4*)(vr + 4 * q) = make_float4(vp0, vp1, vp2, vp3);
                cur = nxt;
            }
        } else if (tid < 192) {
            // ---------------- conv ----------------
            const int p = tid - 64;
            if (T + 1 < NTILES) {
                {
                    int g = (T + 1) * TILE - 15 + p;   // >= 113, valid
                    float val = xb[g];
                    xs[p] = val;
                    if (p >= 1) xsh[p - 1] = val;
                }
                if (p < 15) {
                    int idx = 128 + p;
                    float val = xb[(T + 1) * TILE - 15 + idx];
                    xs[idx] = val;
                    xsh[idx - 1] = val;
                }
                asm volatile("bar.sync 1, 128;" ::: "memory");
                conv_do(qh, xs, xsh, w2, bias2,
                        Ibuf + ((T + 1) & 1) * TSZ + f_loc * RS);
            }
        } else {
            // ---------------- flush ----------------
            const int ft = tid - 192;
            const int r0 = ft >> 5, tq = ft & 31;    // warp covers full rows
            const float* ib  = Ibuf + buf * TSZ;
            const float* vpb = tvp + (buf ^ 1) * TSZ;
            const size_t tcol = (size_t)T * TILE + tq * 4;
            const size_t pcol = (size_t)(T - 1) * TILE + tq * 4;
            float4 mx = make_float4(-1e30f, -1e30f, -1e30f, -1e30f);
#pragma unroll
            for (int i = 0; i < 32; ++i) {
                const int r = r0 + 2 * i;
                const size_t grow = (size_t)(frow0 + r) * LL;
                float4 iq = *(const float4*)(ib + r * RS + tq * 4);
                stcs4(I_out + grow + tcol, iq);
                if (T >= 1) {
                    float4 vq = *(const float4*)(vpb + r * RS + tq * 4);
                    float4 sq, vn;
                    sq.x = (vq.x >= 1.0f) ? 1.0f : 0.0f;
                    sq.y = (vq.y >= 1.0f) ? 1.0f : 0.0f;
                    sq.z = (vq.z >= 1.0f) ? 1.0f : 0.0f;
                    sq.w = (vq.w >= 1.0f) ? 1.0f : 0.0f;
                    vn.x = (vq.x >= 1.0f) ? 0.0f : vq.x;
                    vn.y = (vq.y >= 1.0f) ? 0.0f : vq.y;
                    vn.z = (vq.z >= 1.0f) ? 0.0f : vq.z;
                    vn.w = (vq.w >= 1.0f) ? 0.0f : vq.w;
                    stcs4(vpre_out + grow + pcol, vq);
                    stcs4(v_out    + grow + pcol, vn);
                    stcs4(s_out    + grow + pcol, sq);
                    mx = max4(mx, vq);
                }
            }
            if (T >= 1) {
                *(float4*)(red + ft * 4) = mx;
                asm volatile("bar.sync 3, 64;" ::: "memory");
                if (ft < 32) {
                    float4 a  = *(float4*)(red + ft * 4);
                    float4 b4 = *(float4*)(red + (32 + ft) * 4);
                    a = max4(a, b4);
                    *(float4*)(prow + (size_t)(T - 1) * TILE + ft * 4) = a;
                }
            }
        }
        __syncthreads();
    }

    // ---- epilogue: flush v_pre/v/s + partial max of tile 63 (buffer 1) ----
    if (tid >= 192) {
        const int ft = tid - 192;
        const int r0 = ft >> 5, tq = ft & 31;
        const float* vpb = tvp + ((NTILES - 1) & 1) * TSZ;
        const size_t pcol = (size_t)(NTILES - 1) * TILE + tq * 4;
        float4 mx = make_float4(-1e30f, -1e30f, -1e30f, -1e30f);
#pragma unroll
        for (int i = 0; i < 32; ++i) {
            const int r = r0 + 2 * i;
            const size_t grow = (size_t)(frow0 + r) * LL;
            float4 vq = *(const float4*)(vpb + r * RS + tq * 4);
            float4 sq, vn;
            sq.x = (vq.x >= 1.0f) ? 1.0f : 0.0f;
            sq.y = (vq.y >= 1.0f) ? 1.0f : 0.0f;
            sq.z = (vq.z >= 1.0f) ? 1.0f : 0.0f;
            sq.w = (vq.w >= 1.0f) ? 1.0f : 0.0f;
            vn.x = (vq.x >= 1.0f) ? 0.0f : vq.x;
            vn.y = (vq.y >= 1.0f) ? 0.0f : vq.y;
            vn.z = (vq.z >= 1.0f) ? 0.0f : vq.z;
            vn.w = (vq.w >= 1.0f) ? 0.0f : vq.w;
            stcs4(vpre_out + grow + pcol, vq);
            stcs4(v_out    + grow + pcol, vn);
            stcs4(s_out    + grow + pcol, sq);
            mx = max4(mx, vq);
        }
        *(float4*)(red + ft * 4) = mx;
        asm volatile("bar.sync 3, 64;" ::: "memory");
        if (ft < 32) {
            float4 a  = *(float4*)(red + ft * 4);
            float4 b4 = *(float4*)(red + (32 + ft) * 4);
            a = max4(a, b4);
            *(float4*)(prow + (size_t)(NTILES - 1) * TILE + ft * 4) = a;
        }
    }
}

// ---------------------------------------------------------------------------
// Combine the two filter-half partial maxes into logits.
// MLP=4: each thread owns two float4 column-pairs (4 independent loads) so
// L2 latency (~234cyc) is double-covered; 65536 threads.
// ---------------------------------------------------------------------------
__global__ __launch_bounds__(256) void logits_kernel(float* __restrict__ logits)
{
    int i = blockIdx.x * blockDim.x + threadIdx.x;   // 0 .. BB*LL/8-1
    int b  = i >> 10;                                // 1024 pair-groups/batch
    int l4 = (i & 1023) * 2;                         // float4 index (even)
    const float4* p0 = (const float4*)(g_partial + (size_t)(2 * b) * LL) + l4;
    const float4* p1 = (const float4*)(g_partial + (size_t)(2 * b + 1) * LL) + l4;
    float4 a0 = p0[0], c0 = p1[0];
    float4 a1 = p0[1], c1 = p1[1];
    float4 m0 = max4(a0, c0);
    float4 m1 = max4(a1, c1);
    m0.x -= 1.0f; m0.y -= 1.0f; m0.z -= 1.0f; m0.w -= 1.0f;
    m1.x -= 1.0f; m1.y -= 1.0f; m1.z -= 1.0f; m1.w -= 1.0f;
    float* dst = logits + (size_t)b * LL + l4 * 4;
    stcs4(dst,     m0);
    stcs4(dst + 4, m1);
}

extern "C" void kernel_launch(void* const* d_in, const int* in_sizes, int n_in,
                              void* d_out, int out_size)
{
    const float* x    = (const float*)d_in[0];
    const float* W    = (const float*)d_in[1];
    const float* bias = (const float*)d_in[2];
    float* out = (float*)d_out;

    const size_t N = (size_t)BB * FF * LL;   // 67,108,864
    float* I    = out;
    float* vpre = out + N;
    float* vv   = out + 2 * N;
    float* ss   = out + 3 * N;
    float* lg   = out + 4 * N;

    const int smem_bytes = (4 * TSZ + 144 + 144 + 256) * sizeof(float); // ~137.4KB
    cudaFuncSetAttribute(snn_fused,
                         cudaFuncAttributeMaxDynamicSharedMemorySize, smem_bytes);

    snn_fused<<<128, 256, smem_bytes>>>(x, W, bias, I, vpre, vv, ss);
    logits_kernel<<<(BB * LL / 8) / 256, 256>>>(lg);
}